// round 16
// baseline (speedup 1.0000x reference)
#include <cuda_runtime.h>

// Leapfrog (KDK), softened point mass: a = -q / (r*(r+1)^2 + 1e-12).
//
// v15 = merge of the two equal-fastest variants, keeping only proven wins:
//  - v12's g-update: plain-seed, TWO Newton iterations (no clamps, no
//    extrapolation state; rel_err 2.35e-5, 40x margin) — v14's extrapolated
//    Halley ran the same speed with 15x worse error and 2 alu clamps.
//  - v14's exact slot-saver: s = fma(r2, u, 1) (r never materialized).
//  - block=32 -> 4096 CTAs: per-SM load 27-28 (3.6% imbalance) vs
//    block=64/2048's 13-14 (7.7%). Duration tracks the heaviest SM.
// 18 issue-slots/step (v12: 19, v14: ~20), 1 MUFU/step.
//
// Inputs: d_in[0]=ts f32[N], d_in[1]=w0_lead f32[N,6], d_in[2]=w0_trail f32[N,6],
//         d_in[3]=n_steps i32. Output f32[2N,6]: row 2i=trail_i, 2i+1=lead_i.

__device__ __forceinline__ float rsqrt_ap(float x) {
    float r; asm("rsqrt.approx.f32 %0, %1;" : "=f"(r) : "f"(x)); return r;
}

__device__ __forceinline__ void drift3(float& qx, float& qy, float& qz,
                                       float px, float py, float pz, float dt) {
    qx = fmaf(dt, px, qx);
    qy = fmaf(dt, py, qy);
    qz = fmaf(dt, pz, qz);
}

// Full-accuracy accel eval (2 MUFU), seeds g = 1/(1+r) and applies kick.
__device__ __forceinline__ void kick_init(float& qx, float& qy, float& qz,
                                          float& px, float& py, float& pz,
                                          float ncoef, float& g) {
    float r2 = fmaf(qx, qx, fmaf(qy, qy, qz * qz));
    float u  = rsqrt_ap(r2);             // 1/r
    float s  = fmaf(r2, u, 1.0f);        // 1 + r
    g        = rsqrt_ap(s * s);          // 1/(1+r)
    float sc = (ncoef * u) * (g * g);    // -coef/(r(1+r)^2)
    px = fmaf(sc, qx, px);
    py = fmaf(sc, qy, py);
    pz = fmaf(sc, qz, pz);
}

// Fast kick: 1 MUFU; g refreshed from last step's value by 2 Newton steps
// (seed error ~ |dg|/step ~ 7e-2 worst; e_after ~ e^4 ~ 2.4e-5, proven v12).
__device__ __forceinline__ void kick_fast(float& qx, float& qy, float& qz,
                                          float& px, float& py, float& pz,
                                          float ncoef, float& g) {
    float r2 = fmaf(qx, qx, fmaf(qy, qy, qz * qz));
    float u  = rsqrt_ap(r2);             // only MUFU
    float s  = fmaf(r2, u, 1.0f);        // 1 + r  (r never materialized)
    float t0 = fmaf(-s, g, 2.0f);  g = g * t0;   // Newton #1
    float t1 = fmaf(-s, g, 2.0f);  g = g * t1;   // Newton #2
    float sc = (ncoef * u) * (g * g);    // -coef/(r(1+r)^2)
    px = fmaf(sc, qx, px);
    py = fmaf(sc, qy, py);
    pz = fmaf(sc, qz, pz);
}

template <int INTERIOR, bool FULL_UNROLL>
__device__ __forceinline__ void integrate(float& qx, float& qy, float& qz,
                                          float& px, float& py, float& pz,
                                          float dt, int interior_rt) {
    float nhdt = -0.5f * dt;
    float ndt  = -dt;
    float g;

    kick_init(qx, qy, qz, px, py, pz, nhdt, g);
    if (FULL_UNROLL) {
        #pragma unroll
        for (int s = 0; s < INTERIOR; ++s) {
            drift3(qx, qy, qz, px, py, pz, dt);
            kick_fast(qx, qy, qz, px, py, pz, ndt, g);
        }
    } else {
        #pragma unroll 4
        for (int s = 0; s < interior_rt; ++s) {
            drift3(qx, qy, qz, px, py, pz, dt);
            kick_fast(qx, qy, qz, px, py, pz, ndt, g);
        }
    }
    drift3(qx, qy, qz, px, py, pz, dt);
    kick_fast(qx, qy, qz, px, py, pz, nhdt, g);
}

__global__ void __launch_bounds__(32)
leapfrog_v15_kernel(const float* __restrict__ ts,
                    const float* __restrict__ w0_lead,
                    const float* __restrict__ w0_trail,
                    const int*   __restrict__ n_steps_ptr,
                    float* __restrict__ out,
                    int N) {
    int tid = blockIdx.x * blockDim.x + threadIdx.x;
    if (tid >= 2 * N) return;

    int b = (tid >= N) ? 1 : 0;        // 0 = trail, 1 = lead
    int i = tid - b * N;

    const float* __restrict__ w0 = b ? w0_lead : w0_trail;

    int n_steps = *n_steps_ptr;
    float t_f = ts[N - 1] + 0.001f;    // broadcast, L2-resident

    const float2* __restrict__ row = reinterpret_cast<const float2*>(w0 + 6 * i);
    float2 v0 = row[0];
    float2 v1 = row[1];
    float2 v2 = row[2];
    float qx = v0.x, qy = v0.y, qz = v1.x;
    float px = v1.y, py = v2.x, pz = v2.y;

    if (n_steps == 64) {
        float dt = (t_f - ts[i]) * 0.015625f;   // exact /64
        integrate<63, true>(qx, qy, qz, px, py, pz, dt, 63);
    } else {
        float dt = (t_f - ts[i]) / (float)n_steps;
        integrate<0, false>(qx, qy, qz, px, py, pz, dt, n_steps - 1);
    }

    int orow = 2 * i + b;
    float2* __restrict__ orow_p = reinterpret_cast<float2*>(out + 6 * orow);
    orow_p[0] = make_float2(qx, qy);
    orow_p[1] = make_float2(qz, px);
    orow_p[2] = make_float2(py, pz);
}

extern "C" void kernel_launch(void* const* d_in, const int* in_sizes, int n_in,
                              void* d_out, int out_size) {
    const float* ts       = (const float*)d_in[0];
    const float* w0_lead  = (const float*)d_in[1];
    const float* w0_trail = (const float*)d_in[2];
    const int*   n_steps  = (const int*)d_in[3];
    float* out = (float*)d_out;

    int N = in_sizes[0];
    int total = 2 * N;
    int threads = 32;                   // 4096 CTAs -> 27-28/SM, 3.6% imbalance
    int blocks = (total + threads - 1) / threads;
    leapfrog_v15_kernel<<<blocks, threads>>>(ts, w0_lead, w0_trail, n_steps, out, N);
}

// round 17
// speedup vs baseline: 1.0336x; 1.0336x over previous
#include <cuda_runtime.h>

// Leapfrog (KDK), softened point mass: a = -q / (r*(r+1)^2 + 1e-12).
//
// v16 = v15 (1 MUFU/step, s = fma(r2,u,1), block=32/4096 balanced CTAs) with
// the g = 1/(1+r) corrector cut from 2 Newtons (4 FMA, e0^4 = 2.35e-5) to one
// plain-seed HALLEY (3 FMA, e0^3 ~ 3.4e-4; v14 measured 3.48e-4 for the same
// class and passed with 2.9x margin). Fused form, no clamps needed: plain
// seed g in (0,1] gives h in (-1,1) so the 1+h+h^2 multiplier is positive.
// 16 fma-class + 1 MUFU per step — fma-class count is the only variable that
// has ever moved this kernel (ledger R1-R15).
//
// Inputs: d_in[0]=ts f32[N], d_in[1]=w0_lead f32[N,6], d_in[2]=w0_trail f32[N,6],
//         d_in[3]=n_steps i32. Output f32[2N,6]: row 2i=trail_i, 2i+1=lead_i.

__device__ __forceinline__ float rsqrt_ap(float x) {
    float r; asm("rsqrt.approx.f32 %0, %1;" : "=f"(r) : "f"(x)); return r;
}

__device__ __forceinline__ void drift3(float& qx, float& qy, float& qz,
                                       float px, float py, float pz, float dt) {
    qx = fmaf(dt, px, qx);
    qy = fmaf(dt, py, qy);
    qz = fmaf(dt, pz, qz);
}

// Full-accuracy accel eval (2 MUFU), seeds g = 1/(1+r) and applies kick.
__device__ __forceinline__ void kick_init(float& qx, float& qy, float& qz,
                                          float& px, float& py, float& pz,
                                          float ncoef, float& g) {
    float r2 = fmaf(qx, qx, fmaf(qy, qy, qz * qz));
    float u  = rsqrt_ap(r2);             // 1/r
    float s  = fmaf(r2, u, 1.0f);        // 1 + r
    g        = rsqrt_ap(s * s);          // 1/(1+r)
    float sc = (ncoef * u) * (g * g);    // -coef/(r(1+r)^2)
    px = fmaf(sc, qx, px);
    py = fmaf(sc, qy, py);
    pz = fmaf(sc, qz, pz);
}

// Fast kick: 1 MUFU; g refreshed from last step's value by one Halley step
// (cubic: e_after ~ e_seed^3).
__device__ __forceinline__ void kick_fast(float& qx, float& qy, float& qz,
                                          float& px, float& py, float& pz,
                                          float ncoef, float& g) {
    float r2 = fmaf(qx, qx, fmaf(qy, qy, qz * qz));
    float u  = rsqrt_ap(r2);             // only MUFU
    float s  = fmaf(r2, u, 1.0f);        // 1 + r
    // Halley toward 1/s: h = 1 - s*g; g *= (1 + h + h^2)
    float h  = fmaf(-s, g, 1.0f);
    float hh = fmaf(h, h, h);            // h + h^2
    g        = fmaf(g, hh, g);
    float sc = (ncoef * u) * (g * g);    // -coef/(r(1+r)^2)
    px = fmaf(sc, qx, px);
    py = fmaf(sc, qy, py);
    pz = fmaf(sc, qz, pz);
}

template <int INTERIOR, bool FULL_UNROLL>
__device__ __forceinline__ void integrate(float& qx, float& qy, float& qz,
                                          float& px, float& py, float& pz,
                                          float dt, int interior_rt) {
    float nhdt = -0.5f * dt;
    float ndt  = -dt;
    float g;

    kick_init(qx, qy, qz, px, py, pz, nhdt, g);
    if (FULL_UNROLL) {
        #pragma unroll
        for (int s = 0; s < INTERIOR; ++s) {
            drift3(qx, qy, qz, px, py, pz, dt);
            kick_fast(qx, qy, qz, px, py, pz, ndt, g);
        }
    } else {
        #pragma unroll 4
        for (int s = 0; s < interior_rt; ++s) {
            drift3(qx, qy, qz, px, py, pz, dt);
            kick_fast(qx, qy, qz, px, py, pz, ndt, g);
        }
    }
    drift3(qx, qy, qz, px, py, pz, dt);
    kick_fast(qx, qy, qz, px, py, pz, nhdt, g);
}

__global__ void __launch_bounds__(32)
leapfrog_v16_kernel(const float* __restrict__ ts,
                    const float* __restrict__ w0_lead,
                    const float* __restrict__ w0_trail,
                    const int*   __restrict__ n_steps_ptr,
                    float* __restrict__ out,
                    int N) {
    int tid = blockIdx.x * blockDim.x + threadIdx.x;
    if (tid >= 2 * N) return;

    int b = (tid >= N) ? 1 : 0;        // 0 = trail, 1 = lead
    int i = tid - b * N;

    const float* __restrict__ w0 = b ? w0_lead : w0_trail;

    int n_steps = *n_steps_ptr;
    float t_f = ts[N - 1] + 0.001f;    // broadcast, L2-resident

    const float2* __restrict__ row = reinterpret_cast<const float2*>(w0 + 6 * i);
    float2 v0 = row[0];
    float2 v1 = row[1];
    float2 v2 = row[2];
    float qx = v0.x, qy = v0.y, qz = v1.x;
    float px = v1.y, py = v2.x, pz = v2.y;

    if (n_steps == 64) {
        float dt = (t_f - ts[i]) * 0.015625f;   // exact /64
        integrate<63, true>(qx, qy, qz, px, py, pz, dt, 63);
    } else {
        float dt = (t_f - ts[i]) / (float)n_steps;
        integrate<0, false>(qx, qy, qz, px, py, pz, dt, n_steps - 1);
    }

    int orow = 2 * i + b;
    float2* __restrict__ orow_p = reinterpret_cast<float2*>(out + 6 * orow);
    orow_p[0] = make_float2(qx, qy);
    orow_p[1] = make_float2(qz, px);
    orow_p[2] = make_float2(py, pz);
}

extern "C" void kernel_launch(void* const* d_in, const int* in_sizes, int n_in,
                              void* d_out, int out_size) {
    const float* ts       = (const float*)d_in[0];
    const float* w0_lead  = (const float*)d_in[1];
    const float* w0_trail = (const float*)d_in[2];
    const int*   n_steps  = (const int*)d_in[3];
    float* out = (float*)d_out;

    int N = in_sizes[0];
    int total = 2 * N;
    int threads = 32;                   // 4096 CTAs -> 27-28/SM, 3.6% imbalance
    int blocks = (total + threads - 1) / threads;
    leapfrog_v16_kernel<<<blocks, threads>>>(ts, w0_lead, w0_trail, n_steps, out, N);
}